// round 16
// baseline (speedup 1.0000x reference)
#include <cuda_runtime.h>
#include <cuda_bf16.h>
#include <mma.h>
#include <cstdint>

using namespace nvcuda;

// Problem constants
#define B_  8
#define S_  128
#define E_  768
#define H_  12
#define D_  64
#define SD_ 8192          // S*D
#define BSROWS 1024       // B*S
#define QKROWS 192        // 2*B*H  (q rows 0..95, k rows 96..191)

// ---------------- device scratch (static allocations only) ----------------
__device__ __nv_bfloat16 g_qa_hi[QKROWS * SD_];  // A operand hi [192, 8192] bf16 (3 MB)
__device__ __nv_bfloat16 g_qa_lo[QKROWS * SD_];  // A operand lo                  (3 MB)
__device__ __nv_bfloat16 g_Rh[(size_t)SD_ * SD_]; // R hi bf16 [8192,8192]  (128 MB)
__device__ __nv_bfloat16 g_Rl[(size_t)SD_ * SD_]; // R lo bf16 [8192,8192]  (128 MB)
__device__ float g_qkr[QKROWS * SD_];            // rotated q/k fp32 [192, 8192]  (6 MB)
__device__ float g_v  [BSROWS * E_];             // v proj [1024, 768]            (3 MB)
__device__ float g_ctx[BSROWS * E_];             // ctx [B][H][S][D] == [1024,768](3 MB)

// split a float into bf16 hi + bf16 lo (hi = rn(x), lo = rn(x - hi))
__device__ __forceinline__ void bsplit(float x, __nv_bfloat16& h, __nv_bfloat16& l) {
    h = __float2bfloat16(x);
    l = __float2bfloat16(x - __bfloat162float(h));
}
__device__ __forceinline__ void split4_store(__nv_bfloat16* ph, __nv_bfloat16* pl, float4 v) {
    __nv_bfloat16 h[4], l[4];
    bsplit(v.x, h[0], l[0]); bsplit(v.y, h[1], l[1]);
    bsplit(v.z, h[2], l[2]); bsplit(v.w, h[3], l[3]);
    *(__nv_bfloat162*)(ph)     = __halves2bfloat162(h[0], h[1]);
    *(__nv_bfloat162*)(ph + 2) = __halves2bfloat162(h[2], h[3]);
    *(__nv_bfloat162*)(pl)     = __halves2bfloat162(l[0], l[1]);
    *(__nv_bfloat162*)(pl + 2) = __halves2bfloat162(l[2], l[3]);
}

// ==================== R pre-conversion: fp32 -> bf16 hi/lo (bandwidth-bound) ====================
__global__ void __launch_bounds__(256)
convert_R_kernel(const float* __restrict__ R)
{
    const size_t n4 = (size_t)SD_ * SD_ / 4;     // 16.8M float4s
    const size_t stride = (size_t)gridDim.x * blockDim.x;
    for (size_t i = (size_t)blockIdx.x * blockDim.x + threadIdx.x; i < n4; i += stride) {
        const float4 v = ((const float4*)R)[i];
        __nv_bfloat16 h[4], l[4];
        bsplit(v.x, h[0], l[0]); bsplit(v.y, h[1], l[1]);
        bsplit(v.z, h[2], l[2]); bsplit(v.w, h[3], l[3]);
        union { __nv_bfloat162 b2[2]; uint2 u; } uh, ul;
        uh.b2[0] = __halves2bfloat162(h[0], h[1]);
        uh.b2[1] = __halves2bfloat162(h[2], h[3]);
        ul.b2[0] = __halves2bfloat162(l[0], l[1]);
        ul.b2[1] = __halves2bfloat162(l[2], l[3]);
        *(uint2*)(g_Rh + i * 4) = uh.u;
        *(uint2*)(g_Rl + i * 4) = ul.u;
    }
}

// ==================== WMMA split GEMM, K=768, CTA tile 64x64 (QKV proj) ====================
// C[m][n] = sum_k A[m][k] * W[n][k].  8 warps (2m x 4n), warp tile 32x16, 3-pass bf16 split.
// z=2 (V): fp32 store to g_v.  z=0/1 (Q/K): split-scatter to g_qa_*.
__global__ void __launch_bounds__(256, 2)
wproj_kernel(const float* __restrict__ X,
             const float* __restrict__ Wq,
             const float* __restrict__ Wk,
             const float* __restrict__ Wv)
{
    __shared__ __nv_bfloat16 sAh[64 * 40], sAl[64 * 40];
    __shared__ __nv_bfloat16 sBh[64 * 40], sBl[64 * 40];

    const float* W; int epi, base;
    if (blockIdx.z == 0)      { W = Wq; epi = 1; base = 0;  }
    else if (blockIdx.z == 1) { W = Wk; epi = 1; base = 96; }
    else                      { W = Wv; epi = 0; base = 0;  }

    const int tid  = threadIdx.x;
    const int wid  = tid >> 5;
    const int lane = tid & 31;
    const int wm   = wid >> 2;      // 0..1 -> m offset wm*32
    const int wn   = wid & 3;       // 0..3 -> n offset wn*16
    const int bm   = blockIdx.y * 64;
    const int bn   = blockIdx.x * 64;

    wmma::fragment<wmma::accumulator, 16, 16, 16, float> acc[2];
    #pragma unroll
    for (int i = 0; i < 2; i++) wmma::fill_fragment(acc[i], 0.0f);

    float4 ra[2], rb[2];
    auto ldrs = [&](int t) {
        const int k0 = t * 32;
        #pragma unroll
        for (int u = 0; u < 2; u++) {
            const int i = tid + u * 256;           // 0..511 : 64 rows x 8 float4
            const int r = i >> 3, c = (i & 7) << 2;
            ra[u] = *(const float4*)(X + (size_t)(bm + r) * E_ + k0 + c);
            rb[u] = *(const float4*)(W + (size_t)(bn + r) * E_ + k0 + c);
        }
    };
    auto store_smem = [&]() {
        #pragma unroll
        for (int u = 0; u < 2; u++) {
            const int i = tid + u * 256;
            const int r = i >> 3, c = (i & 7) << 2;
            split4_store(&sAh[r * 40 + c], &sAl[r * 40 + c], ra[u]);
            split4_store(&sBh[r * 40 + c], &sBl[r * 40 + c], rb[u]);
        }
    };

    ldrs(0);
    for (int t = 0; t < 24; ++t) {
        store_smem();
        __syncthreads();
        if (t + 1 < 24) ldrs(t + 1);

        #pragma unroll
        for (int ks = 0; ks < 2; ks++) {
            wmma::fragment<wmma::matrix_a, 16, 16, 16, __nv_bfloat16, wmma::row_major> ah[2], al[2];
            wmma::fragment<wmma::matrix_b, 16, 16, 16, __nv_bfloat16, wmma::col_major> bh, bl;
            #pragma unroll
            for (int i = 0; i < 2; i++) {
                wmma::load_matrix_sync(ah[i], &sAh[(wm * 32 + i * 16) * 40 + ks * 16], 40);
                wmma::load_matrix_sync(al[i], &sAl[(wm * 32 + i * 16) * 40 + ks * 16], 40);
            }
            wmma::load_matrix_sync(bh, &sBh[(wn * 16) * 40 + ks * 16], 40);
            wmma::load_matrix_sync(bl, &sBl[(wn * 16) * 40 + ks * 16], 40);
            #pragma unroll
            for (int i = 0; i < 2; i++) {
                wmma::mma_sync(acc[i], ah[i], bh, acc[i]);
                wmma::mma_sync(acc[i], ah[i], bl, acc[i]);
                wmma::mma_sync(acc[i], al[i], bh, acc[i]);
            }
        }
        __syncthreads();
    }

    // ---- epilogue ----
    if (epi == 0) {
        #pragma unroll
        for (int i = 0; i < 2; i++)
            wmma::store_matrix_sync(
                g_v + (size_t)(bm + wm * 32 + i * 16) * E_ + bn + wn * 16,
                acc[i], E_, wmma::mem_row_major);
    } else {
        // per-warp fp32 staging in dead smem: warps 0..3 -> sAh, 4..7 -> sBh
        float* my = (wid < 4) ? ((float*)sAh + wid * 256)
                              : ((float*)sBh + (wid - 4) * 256);
        #pragma unroll
        for (int i = 0; i < 2; i++) {
            wmma::store_matrix_sync(my, acc[i], 16, wmma::mem_row_major);
            __syncwarp();
            const int rr = lane >> 1, hc = lane & 1;
            const float* src = my + rr * 16 + hc * 8;
            const int gr = bm + wm * 32 + i * 16 + rr;      // 0..1023
            const int gc = bn + wn * 16 + hc * 8;           // multiple of 8, one head
            const int b = gr >> 7, s = gr & 127;
            const int h = gc >> 6, d = gc & 63;
            const size_t off = ((size_t)(base + b * H_ + h) << 13) + s * D_ + d;
            union { __nv_bfloat162 b2[4]; uint4 u; } uh, ul;
            #pragma unroll
            for (int p = 0; p < 4; p++) {
                __nv_bfloat16 h0, l0, h1, l1;
                bsplit(src[p * 2 + 0], h0, l0);
                bsplit(src[p * 2 + 1], h1, l1);
                uh.b2[p] = __halves2bfloat162(h0, h1);
                ul.b2[p] = __halves2bfloat162(l0, l1);
            }
            *(uint4*)(g_qa_hi + off) = uh.u;
            *(uint4*)(g_qa_lo + off) = ul.u;
            __syncwarp();
        }
    }
}

// final: out = ctx @ Wo^T, CTA tile 64x64, grid (12,16)
__global__ void __launch_bounds__(256, 2)
wfinal_kernel(const float* __restrict__ Wo, float* __restrict__ out)
{
    __shared__ __nv_bfloat16 sAh[64 * 40], sAl[64 * 40];
    __shared__ __nv_bfloat16 sBh[64 * 40], sBl[64 * 40];

    const int tid = threadIdx.x;
    const int wid = tid >> 5;
    const int wm  = wid >> 2;
    const int wn  = wid & 3;
    const int bm  = blockIdx.y * 64;
    const int bn  = blockIdx.x * 64;

    wmma::fragment<wmma::accumulator, 16, 16, 16, float> acc[2];
    #pragma unroll
    for (int i = 0; i < 2; i++) wmma::fill_fragment(acc[i], 0.0f);

    float4 ra[2], rb[2];
    auto ldrs = [&](int t) {
        const int k0 = t * 32;
        #pragma unroll
        for (int u = 0; u < 2; u++) {
            const int i = tid + u * 256;
            const int r = i >> 3, c = (i & 7) << 2;
            ra[u] = *(const float4*)(g_ctx + (size_t)(bm + r) * E_ + k0 + c);
            rb[u] = *(const float4*)(Wo + (size_t)(bn + r) * E_ + k0 + c);
        }
    };
    auto store_smem = [&]() {
        #pragma unroll
        for (int u = 0; u < 2; u++) {
            const int i = tid + u * 256;
            const int r = i >> 3, c = (i & 7) << 2;
            split4_store(&sAh[r * 40 + c], &sAl[r * 40 + c], ra[u]);
            split4_store(&sBh[r * 40 + c], &sBl[r * 40 + c], rb[u]);
        }
    };

    ldrs(0);
    for (int t = 0; t < 24; ++t) {
        store_smem();
        __syncthreads();
        if (t + 1 < 24) ldrs(t + 1);
        #pragma unroll
        for (int ks = 0; ks < 2; ks++) {
            wmma::fragment<wmma::matrix_a, 16, 16, 16, __nv_bfloat16, wmma::row_major> ah[2], al[2];
            wmma::fragment<wmma::matrix_b, 16, 16, 16, __nv_bfloat16, wmma::col_major> bh, bl;
            #pragma unroll
            for (int i = 0; i < 2; i++) {
                wmma::load_matrix_sync(ah[i], &sAh[(wm * 32 + i * 16) * 40 + ks * 16], 40);
                wmma::load_matrix_sync(al[i], &sAl[(wm * 32 + i * 16) * 40 + ks * 16], 40);
            }
            wmma::load_matrix_sync(bh, &sBh[(wn * 16) * 40 + ks * 16], 40);
            wmma::load_matrix_sync(bl, &sBl[(wn * 16) * 40 + ks * 16], 40);
            #pragma unroll
            for (int i = 0; i < 2; i++) {
                wmma::mma_sync(acc[i], ah[i], bh, acc[i]);
                wmma::mma_sync(acc[i], ah[i], bl, acc[i]);
                wmma::mma_sync(acc[i], al[i], bh, acc[i]);
            }
        }
        __syncthreads();
    }

    #pragma unroll
    for (int i = 0; i < 2; i++)
        wmma::store_matrix_sync(
            out + (size_t)(bm + wm * 32 + i * 16) * E_ + bn + wn * 16,
            acc[i], E_, wmma::mem_row_major);
}

// ==================== WMMA rotation kernel v3 ====================
// D[192, 8192] = A[192, 8192] @ R[8192, 8192]
// CTA tile 96(M) x 128(N), BK=32.  grid (64 n-tiles, 2 m-tiles) = 128 CTAs, 256 threads,
// 8 warps (2m x 4n), warp tile 48x32 -> 6 acc frags: 36 mma_sync per chunk vs 20 frag loads.
// A pre-split bf16 hi/lo; R pre-split bf16 hi/lo -> loaders are pure uint2 copies.
// Register-prefetch pipeline: loads for chunk t+1 issue before MMAs of chunk t.
#define RBK 32
#define RBN 128
#define RNCH (SD_ / RBK)      // 256 chunks
#define RA_LDM 40
#define RB_LDM 136

__global__ void __launch_bounds__(256, 1)
rot_wmma_kernel()
{
    __shared__ __nv_bfloat16 sAh[96 * RA_LDM], sAl[96 * RA_LDM];   // 2 x 7.7 KB
    __shared__ __nv_bfloat16 sBh[RBK * RB_LDM], sBl[RBK * RB_LDM]; // 2 x 8.7 KB

    const int tid = threadIdx.x;
    const int wid = tid >> 5;
    const int wm  = wid >> 2;       // 0..1 -> m offset wm*48
    const int wn  = wid & 3;        // 0..3 -> n offset wn*32
    const int n0  = blockIdx.x * RBN;
    const int m0  = blockIdx.y * 96;

    wmma::fragment<wmma::accumulator, 16, 16, 16, float> acc[3][2];
    #pragma unroll
    for (int i = 0; i < 3; i++)
        #pragma unroll
        for (int j = 0; j < 2; j++) wmma::fill_fragment(acc[i][j], 0.0f);

    uint2 pah[3], pal[3];
    uint2 pbh[4], pbl[4];
    auto ldrs = [&](int t) {
        const int k0 = t * RBK;
        #pragma unroll
        for (int u = 0; u < 3; u++) {
            const int i = tid + u * 256;          // 0..767 : 96 rows x 8 uint2
            const int r = i >> 3, c = (i & 7) << 2;
            pah[u] = *(const uint2*)(g_qa_hi + (size_t)(m0 + r) * SD_ + k0 + c);
            pal[u] = *(const uint2*)(g_qa_lo + (size_t)(m0 + r) * SD_ + k0 + c);
        }
        #pragma unroll
        for (int u = 0; u < 4; u++) {
            const int i = tid + u * 256;          // 0..1023 : 32 k-rows x 32 uint2
            const int kk = i >> 5, n4 = (i & 31) << 2;
            pbh[u] = *(const uint2*)(g_Rh + (size_t)(k0 + kk) * SD_ + n0 + n4);
            pbl[u] = *(const uint2*)(g_Rl + (size_t)(k0 + kk) * SD_ + n0 + n4);
        }
    };
    auto store_smem = [&]() {
        #pragma unroll
        for (int u = 0; u < 3; u++) {
            const int i = tid + u * 256;
            const int r = i >> 3, c = (i & 7) << 2;
            *(uint2*)&sAh[r * RA_LDM + c] = pah[u];
            *(uint2*)&sAl[r * RA_LDM + c] = pal[u];
        }
        #pragma unroll
        for (int u = 0; u < 4; u++) {
            const int i = tid + u * 256;
            const int kk = i >> 5, n4 = (i & 31) << 2;
            *(uint2*)&sBh[kk * RB_LDM + n4] = pbh[u];
            *(uint2*)&sBl[kk * RB_LDM + n4] = pbl[u];
        }
    };

    ldrs(0);
    for (int t = 0; t < RNCH; ++t) {
        store_smem();
        __syncthreads();
        if (t + 1 < RNCH) ldrs(t + 1);

        #pragma unroll
        for (int ks = 0; ks < 2; ks++) {
            wmma::fragment<wmma::matrix_a, 16, 16, 16, __nv_bfloat16, wmma::row_major> ah[3], al[3];
            wmma::fragment<wmma::matrix_b, 16, 16, 16, __nv_bfloat16, wmma::row_major> bh[2], bl[2];
            #pragma unroll
            for (int i = 0; i < 3; i++) {
                wmma::load_matrix_sync(ah[i], &sAh[(wm * 48 + i * 16) * RA_LDM + ks * 16], RA_LDM);
                wmma::load_matrix_sync(al[i], &sAl[(wm * 48 + i * 16) * RA_LDM + ks * 16], RA_LDM);
            }
            #pragma unroll
            for (int j = 0; j < 2; j++) {
                wmma::load_matrix_sync(bh[j], &sBh[(ks * 16) * RB_LDM + wn * 32 + j * 16], RB_LDM);
                wmma::load_matrix_sync(bl[j], &sBl[(ks * 16) * RB_LDM + wn * 32 + j * 16], RB_LDM);
            }
            #pragma unroll
            for (int i = 0; i < 3; i++)
                #pragma unroll
                for (int j = 0; j < 2; j++) {
                    wmma::mma_sync(acc[i][j], ah[i], bh[j], acc[i][j]);
                    wmma::mma_sync(acc[i][j], ah[i], bl[j], acc[i][j]);
                    wmma::mma_sync(acc[i][j], al[i], bh[j], acc[i][j]);
                }
        }
        __syncthreads();
    }

    #pragma unroll
    for (int i = 0; i < 3; i++)
        #pragma unroll
        for (int j = 0; j < 2; j++)
            wmma::store_matrix_sync(
                g_qkr + (size_t)(m0 + wm * 48 + i * 16) * SD_ + n0 + wn * 32 + j * 16,
                acc[i][j], SD_, wmma::mem_row_major);
}

// ==================== per-(b,s) head-axis attention ====================
#define ATTN_THREADS 192
__global__ void __launch_bounds__(ATTN_THREADS)
attn_kernel(const float* __restrict__ mask,
            float* __restrict__ attn_out,
            int write_attn)
{
    const int bs = blockIdx.x;
    const int b  = bs >> 7;
    const int s  = bs & 127;
    const int tid = threadIdx.x;

    __shared__ float qs[H_ * D_];
    __shared__ float ks[H_ * D_];
    __shared__ float vs[H_ * D_];
    __shared__ float aw[H_ * H_];

    for (int i = tid; i < H_ * D_; i += ATTN_THREADS) {
        const int h = i >> 6, d = i & 63;
        qs[i] = g_qkr[(((size_t)(b * H_ + h)) << 13) + s * D_ + d];
        ks[i] = g_qkr[(((size_t)(96 + b * H_ + h)) << 13) + s * D_ + d];
        vs[i] = g_v[(size_t)bs * E_ + i];
    }
    __syncthreads();

    if (tid < H_ * H_) {
        const int h = tid / H_, g = tid % H_;
        float acc = 0.0f;
        #pragma unroll
        for (int d = 0; d < D_; d++) acc += qs[h * D_ + d] * ks[g * D_ + d];
        aw[tid] = acc * 0.125f + mask[b * (H_ * H_) + tid];
    }
    __syncthreads();

    if (tid < H_) {
        float mx = -3.0e38f;
        #pragma unroll
        for (int g = 0; g < H_; g++) mx = fmaxf(mx, aw[tid * H_ + g]);
        float e[H_];
        float sum = 0.0f;
        #pragma unroll
        for (int g = 0; g < H_; g++) { e[g] = expf(aw[tid * H_ + g] - mx); sum += e[g]; }
        const float inv = 1.0f / sum;
        #pragma unroll
        for (int g = 0; g < H_; g++) aw[tid * H_ + g] = e[g] * inv;
    }
    __syncthreads();

    if (write_attn && tid < H_ * H_)
        attn_out[(size_t)bs * (H_ * H_) + tid] = aw[tid];

    for (int i = tid; i < H_ * D_; i += ATTN_THREADS) {
        const int h = i >> 6, d = i & 63;
        float acc = 0.0f;
        #pragma unroll
        for (int g = 0; g < H_; g++) acc += aw[h * H_ + g] * vs[g * D_ + d];
        g_ctx[(size_t)b * (H_ * S_ * D_) + h * (S_ * D_) + s * D_ + d] = acc;
    }
}

// ---------------- launch ----------------
extern "C" void kernel_launch(void* const* d_in, const int* in_sizes, int n_in,
                              void* d_out, int out_size)
{
    const float* hidden = (const float*)d_in[0];
    const float* R      = (const float*)d_in[1];
    const float* mask   = (const float*)d_in[2];
    const float* Wq     = (const float*)d_in[3];
    const float* Wk     = (const float*)d_in[4];
    const float* Wv     = (const float*)d_in[5];
    const float* Wo     = (const float*)d_in[6];
    float* out = (float*)d_out;

    const int OUT_ELEMS  = B_ * S_ * E_;
    const int ATTN_ELEMS = B_ * S_ * H_ * H_;
    const int write_attn = (out_size >= OUT_ELEMS + ATTN_ELEMS) ? 1 : 0;

    // 0) pre-split R into bf16 hi/lo (bandwidth-bound, once)
    convert_R_kernel<<<148 * 8, 256>>>(R);

    // 1) WMMA QKV projections, 64x64 tiles (q,k -> split rotated layout; v -> g_v)
    wproj_kernel<<<dim3(E_ / 64, BSROWS / 64, 3), 256>>>(hidden, Wq, Wk, Wv);

    // 2) WMMA rotation v3: 96x128 tiles, warp tile 48x32, pure-copy loaders
    rot_wmma_kernel<<<dim3(SD_ / RBN, 2), 256>>>();

    // 3) per-position head-axis attention
    attn_kernel<<<BSROWS, ATTN_THREADS>>>(mask, out + OUT_ELEMS, write_attn);

    // 4) WMMA output projection -> d_out
    wfinal_kernel<<<dim3(E_ / 64, BSROWS / 64), 256>>>(Wo, out);
}

// round 17
// speedup vs baseline: 1.1285x; 1.1285x over previous
#include <cuda_runtime.h>
#include <cuda_bf16.h>
#include <mma.h>
#include <cstdint>

using namespace nvcuda;

// Problem constants
#define B_  8
#define S_  128
#define E_  768
#define H_  12
#define D_  64
#define SD_ 8192          // S*D
#define BSROWS 1024       // B*S
#define QKROWS 192        // 2*B*H  (q rows 0..95, k rows 96..191)

// ---------------- device scratch (static allocations only) ----------------
__device__ __nv_bfloat16 g_qa_hi[QKROWS * SD_];  // A operand hi [192, 8192] bf16 (3 MB)
__device__ __nv_bfloat16 g_qa_lo[QKROWS * SD_];  // A operand lo                  (3 MB)
__device__ float g_qkr[QKROWS * SD_];            // rotated q/k fp32 [192, 8192]  (6 MB)
__device__ float g_v  [BSROWS * E_];             // v proj [1024, 768]            (3 MB)
__device__ float g_ctx[BSROWS * E_];             // ctx [B][H][S][D] == [1024,768](3 MB)

// split a float into bf16 hi + bf16 lo (hi = rn(x), lo = rn(x - hi))
__device__ __forceinline__ void bsplit(float x, __nv_bfloat16& h, __nv_bfloat16& l) {
    h = __float2bfloat16(x);
    l = __float2bfloat16(x - __bfloat162float(h));
}
__device__ __forceinline__ void split4_store(__nv_bfloat16* ph, __nv_bfloat16* pl, float4 v) {
    __nv_bfloat16 h[4], l[4];
    bsplit(v.x, h[0], l[0]); bsplit(v.y, h[1], l[1]);
    bsplit(v.z, h[2], l[2]); bsplit(v.w, h[3], l[3]);
    *(__nv_bfloat162*)(ph)     = __halves2bfloat162(h[0], h[1]);
    *(__nv_bfloat162*)(ph + 2) = __halves2bfloat162(h[2], h[3]);
    *(__nv_bfloat162*)(pl)     = __halves2bfloat162(l[0], l[1]);
    *(__nv_bfloat162*)(pl + 2) = __halves2bfloat162(l[2], l[3]);
}

// ==================== WMMA split GEMM, K=768, CTA tile 64x64 (QKV proj) ====================
// C[m][n] = sum_k A[m][k] * W[n][k].  8 warps (2m x 4n), warp tile 32x16, 3-pass bf16 split.
// z=2 (V): fp32 store to g_v.  z=0/1 (Q/K): split-scatter to g_qa_*.
__global__ void __launch_bounds__(256, 2)
wproj_kernel(const float* __restrict__ X,
             const float* __restrict__ Wq,
             const float* __restrict__ Wk,
             const float* __restrict__ Wv)
{
    __shared__ __nv_bfloat16 sAh[64 * 40], sAl[64 * 40];
    __shared__ __nv_bfloat16 sBh[64 * 40], sBl[64 * 40];

    const float* W; int epi, base;
    if (blockIdx.z == 0)      { W = Wq; epi = 1; base = 0;  }
    else if (blockIdx.z == 1) { W = Wk; epi = 1; base = 96; }
    else                      { W = Wv; epi = 0; base = 0;  }

    const int tid  = threadIdx.x;
    const int wid  = tid >> 5;
    const int lane = tid & 31;
    const int wm   = wid >> 2;      // 0..1 -> m offset wm*32
    const int wn   = wid & 3;       // 0..3 -> n offset wn*16
    const int bm   = blockIdx.y * 64;
    const int bn   = blockIdx.x * 64;

    wmma::fragment<wmma::accumulator, 16, 16, 16, float> acc[2];
    #pragma unroll
    for (int i = 0; i < 2; i++) wmma::fill_fragment(acc[i], 0.0f);

    float4 ra[2], rb[2];
    auto ldrs = [&](int t) {
        const int k0 = t * 32;
        #pragma unroll
        for (int u = 0; u < 2; u++) {
            const int i = tid + u * 256;           // 0..511 : 64 rows x 8 float4
            const int r = i >> 3, c = (i & 7) << 2;
            ra[u] = *(const float4*)(X + (size_t)(bm + r) * E_ + k0 + c);
            rb[u] = *(const float4*)(W + (size_t)(bn + r) * E_ + k0 + c);
        }
    };
    auto store_smem = [&]() {
        #pragma unroll
        for (int u = 0; u < 2; u++) {
            const int i = tid + u * 256;
            const int r = i >> 3, c = (i & 7) << 2;
            split4_store(&sAh[r * 40 + c], &sAl[r * 40 + c], ra[u]);
            split4_store(&sBh[r * 40 + c], &sBl[r * 40 + c], rb[u]);
        }
    };

    ldrs(0);
    for (int t = 0; t < 24; ++t) {
        store_smem();
        __syncthreads();
        if (t + 1 < 24) ldrs(t + 1);

        #pragma unroll
        for (int ks = 0; ks < 2; ks++) {
            wmma::fragment<wmma::matrix_a, 16, 16, 16, __nv_bfloat16, wmma::row_major> ah[2], al[2];
            wmma::fragment<wmma::matrix_b, 16, 16, 16, __nv_bfloat16, wmma::col_major> bh, bl;
            #pragma unroll
            for (int i = 0; i < 2; i++) {
                wmma::load_matrix_sync(ah[i], &sAh[(wm * 32 + i * 16) * 40 + ks * 16], 40);
                wmma::load_matrix_sync(al[i], &sAl[(wm * 32 + i * 16) * 40 + ks * 16], 40);
            }
            wmma::load_matrix_sync(bh, &sBh[(wn * 16) * 40 + ks * 16], 40);
            wmma::load_matrix_sync(bl, &sBl[(wn * 16) * 40 + ks * 16], 40);
            #pragma unroll
            for (int i = 0; i < 2; i++) {
                wmma::mma_sync(acc[i], ah[i], bh, acc[i]);
                wmma::mma_sync(acc[i], ah[i], bl, acc[i]);
                wmma::mma_sync(acc[i], al[i], bh, acc[i]);
            }
        }
        __syncthreads();
    }

    // ---- epilogue ----
    if (epi == 0) {
        #pragma unroll
        for (int i = 0; i < 2; i++)
            wmma::store_matrix_sync(
                g_v + (size_t)(bm + wm * 32 + i * 16) * E_ + bn + wn * 16,
                acc[i], E_, wmma::mem_row_major);
    } else {
        // per-warp fp32 staging in dead smem: warps 0..3 -> sAh, 4..7 -> sBh
        float* my = (wid < 4) ? ((float*)sAh + wid * 256)
                              : ((float*)sBh + (wid - 4) * 256);
        #pragma unroll
        for (int i = 0; i < 2; i++) {
            wmma::store_matrix_sync(my, acc[i], 16, wmma::mem_row_major);
            __syncwarp();
            const int rr = lane >> 1, hc = lane & 1;
            const float* src = my + rr * 16 + hc * 8;
            const int gr = bm + wm * 32 + i * 16 + rr;      // 0..1023
            const int gc = bn + wn * 16 + hc * 8;           // multiple of 8, one head
            const int b = gr >> 7, s = gr & 127;
            const int h = gc >> 6, d = gc & 63;
            const size_t off = ((size_t)(base + b * H_ + h) << 13) + s * D_ + d;
            union { __nv_bfloat162 b2[4]; uint4 u; } uh, ul;
            #pragma unroll
            for (int p = 0; p < 4; p++) {
                __nv_bfloat16 h0, l0, h1, l1;
                bsplit(src[p * 2 + 0], h0, l0);
                bsplit(src[p * 2 + 1], h1, l1);
                uh.b2[p] = __halves2bfloat162(h0, h1);
                ul.b2[p] = __halves2bfloat162(l0, l1);
            }
            *(uint4*)(g_qa_hi + off) = uh.u;
            *(uint4*)(g_qa_lo + off) = ul.u;
            __syncwarp();
        }
    }
}

// final: out = ctx @ Wo^T, CTA tile 64x64, grid (12,16)
__global__ void __launch_bounds__(256, 2)
wfinal_kernel(const float* __restrict__ Wo, float* __restrict__ out)
{
    __shared__ __nv_bfloat16 sAh[64 * 40], sAl[64 * 40];
    __shared__ __nv_bfloat16 sBh[64 * 40], sBl[64 * 40];

    const int tid = threadIdx.x;
    const int wid = tid >> 5;
    const int wm  = wid >> 2;
    const int wn  = wid & 3;
    const int bm  = blockIdx.y * 64;
    const int bn  = blockIdx.x * 64;

    wmma::fragment<wmma::accumulator, 16, 16, 16, float> acc[2];
    #pragma unroll
    for (int i = 0; i < 2; i++) wmma::fill_fragment(acc[i], 0.0f);

    float4 ra[2], rb[2];
    auto ldrs = [&](int t) {
        const int k0 = t * 32;
        #pragma unroll
        for (int u = 0; u < 2; u++) {
            const int i = tid + u * 256;
            const int r = i >> 3, c = (i & 7) << 2;
            ra[u] = *(const float4*)(g_ctx + (size_t)(bm + r) * E_ + k0 + c);
            rb[u] = *(const float4*)(Wo + (size_t)(bn + r) * E_ + k0 + c);
        }
    };
    auto store_smem = [&]() {
        #pragma unroll
        for (int u = 0; u < 2; u++) {
            const int i = tid + u * 256;
            const int r = i >> 3, c = (i & 7) << 2;
            split4_store(&sAh[r * 40 + c], &sAl[r * 40 + c], ra[u]);
            split4_store(&sBh[r * 40 + c], &sBl[r * 40 + c], rb[u]);
        }
    };

    ldrs(0);
    for (int t = 0; t < 24; ++t) {
        store_smem();
        __syncthreads();
        if (t + 1 < 24) ldrs(t + 1);
        #pragma unroll
        for (int ks = 0; ks < 2; ks++) {
            wmma::fragment<wmma::matrix_a, 16, 16, 16, __nv_bfloat16, wmma::row_major> ah[2], al[2];
            wmma::fragment<wmma::matrix_b, 16, 16, 16, __nv_bfloat16, wmma::col_major> bh, bl;
            #pragma unroll
            for (int i = 0; i < 2; i++) {
                wmma::load_matrix_sync(ah[i], &sAh[(wm * 32 + i * 16) * 40 + ks * 16], 40);
                wmma::load_matrix_sync(al[i], &sAl[(wm * 32 + i * 16) * 40 + ks * 16], 40);
            }
            wmma::load_matrix_sync(bh, &sBh[(wn * 16) * 40 + ks * 16], 40);
            wmma::load_matrix_sync(bl, &sBl[(wn * 16) * 40 + ks * 16], 40);
            #pragma unroll
            for (int i = 0; i < 2; i++) {
                wmma::mma_sync(acc[i], ah[i], bh, acc[i]);
                wmma::mma_sync(acc[i], ah[i], bl, acc[i]);
                wmma::mma_sync(acc[i], al[i], bh, acc[i]);
            }
        }
        __syncthreads();
    }

    #pragma unroll
    for (int i = 0; i < 2; i++)
        wmma::store_matrix_sync(
            out + (size_t)(bm + wm * 32 + i * 16) * E_ + bn + wn * 16,
            acc[i], E_, wmma::mem_row_major);
}

// ==================== WMMA rotation kernel v4: double-buffered, 1 sync/chunk ====================
// D[192, 8192] = A[192, 8192] @ R[8192, 8192]
// CTA tile 96(M) x 64(N), BK=32.  grid (128 n-tiles, 2 m-tiles) = 256 CTAs, 256 threads,
// 8 warps (2m x 4n), warp tile 48x16, occ 2.  Double-buffered smem (48 KB total):
// MMA(t) reads buf[t&1] while LDG(t+1)+convert+STS fills buf[(t+1)&1] -> one barrier per chunk.
// A pre-split bf16 hi/lo (from proj); R converted fp32->hi/lo inline in the store phase.
#define RBK 32
#define RBN 64
#define RNCH (SD_ / RBK)      // 256 chunks
#define RA_LDM 40
#define RB_LDM 72

__global__ void __launch_bounds__(256, 2)
rot_wmma_kernel(const float* __restrict__ R)
{
    __shared__ __nv_bfloat16 sAh[2][96 * RA_LDM], sAl[2][96 * RA_LDM]; // 2 x 15.0 KB
    __shared__ __nv_bfloat16 sBh[2][RBK * RB_LDM], sBl[2][RBK * RB_LDM]; // 2 x 9.0 KB

    const int tid = threadIdx.x;
    const int wid = tid >> 5;
    const int wm  = wid >> 2;       // 0..1 -> m offset wm*48
    const int wn  = wid & 3;        // 0..3 -> n offset wn*16
    const int n0  = blockIdx.x * RBN;
    const int m0  = blockIdx.y * 96;

    wmma::fragment<wmma::accumulator, 16, 16, 16, float> acc[3];
    #pragma unroll
    for (int i = 0; i < 3; i++) wmma::fill_fragment(acc[i], 0.0f);

    uint2 pah[3], pal[3];
    float4 prb[2];
    auto ldrs = [&](int t) {
        const int k0 = t * RBK;
        #pragma unroll
        for (int u = 0; u < 3; u++) {
            const int i = tid + u * 256;          // 0..767 : 96 rows x 8 uint2
            const int r = i >> 3, c = (i & 7) << 2;
            pah[u] = *(const uint2*)(g_qa_hi + (size_t)(m0 + r) * SD_ + k0 + c);
            pal[u] = *(const uint2*)(g_qa_lo + (size_t)(m0 + r) * SD_ + k0 + c);
        }
        #pragma unroll
        for (int u = 0; u < 2; u++) {
            const int i = tid + u * 256;          // 0..511 : 32 k-rows x 16 float4
            const int kk = i >> 4, n4 = (i & 15) << 2;
            prb[u] = *(const float4*)(R + (size_t)(k0 + kk) * SD_ + n0 + n4);
        }
    };
    auto store_smem = [&](int b) {
        #pragma unroll
        for (int u = 0; u < 3; u++) {
            const int i = tid + u * 256;
            const int r = i >> 3, c = (i & 7) << 2;
            *(uint2*)&sAh[b][r * RA_LDM + c] = pah[u];
            *(uint2*)&sAl[b][r * RA_LDM + c] = pal[u];
        }
        #pragma unroll
        for (int u = 0; u < 2; u++) {
            const int i = tid + u * 256;
            const int kk = i >> 4, n4 = (i & 15) << 2;
            split4_store(&sBh[b][kk * RB_LDM + n4], &sBl[b][kk * RB_LDM + n4], prb[u]);
        }
    };

    // prologue: chunk 0 -> buffer 0
    ldrs(0);
    store_smem(0);
    __syncthreads();

    for (int t = 0; t < RNCH; ++t) {
        const int cur = t & 1;
        const bool hasNext = (t + 1 < RNCH);
        if (hasNext) ldrs(t + 1);          // long-latency loads first

        #pragma unroll
        for (int ks = 0; ks < 2; ks++) {
            wmma::fragment<wmma::matrix_a, 16, 16, 16, __nv_bfloat16, wmma::row_major> ah[3], al[3];
            wmma::fragment<wmma::matrix_b, 16, 16, 16, __nv_bfloat16, wmma::row_major> bh, bl;
            #pragma unroll
            for (int i = 0; i < 3; i++) {
                wmma::load_matrix_sync(ah[i], &sAh[cur][(wm * 48 + i * 16) * RA_LDM + ks * 16], RA_LDM);
                wmma::load_matrix_sync(al[i], &sAl[cur][(wm * 48 + i * 16) * RA_LDM + ks * 16], RA_LDM);
            }
            wmma::load_matrix_sync(bh, &sBh[cur][(ks * 16) * RB_LDM + wn * 16], RB_LDM);
            wmma::load_matrix_sync(bl, &sBl[cur][(ks * 16) * RB_LDM + wn * 16], RB_LDM);
            #pragma unroll
            for (int i = 0; i < 3; i++) {
                wmma::mma_sync(acc[i], ah[i], bh, acc[i]);
                wmma::mma_sync(acc[i], ah[i], bl, acc[i]);
                wmma::mma_sync(acc[i], al[i], bh, acc[i]);
            }
        }

        if (hasNext) store_smem(cur ^ 1);  // fill the other buffer (overlaps with MMAs above)
        __syncthreads();                   // ONE barrier per chunk
    }

    #pragma unroll
    for (int i = 0; i < 3; i++)
        wmma::store_matrix_sync(
            g_qkr + (size_t)(m0 + wm * 48 + i * 16) * SD_ + n0 + wn * 16,
            acc[i], SD_, wmma::mem_row_major);
}

// ==================== per-(b,s) head-axis attention ====================
#define ATTN_THREADS 192
__global__ void __launch_bounds__(ATTN_THREADS)
attn_kernel(const float* __restrict__ mask,
            float* __restrict__ attn_out,
            int write_attn)
{
    const int bs = blockIdx.x;
    const int b  = bs >> 7;
    const int s  = bs & 127;
    const int tid = threadIdx.x;

    __shared__ float qs[H_ * D_];
    __shared__ float ks[H_ * D_];
    __shared__ float vs[H_ * D_];
    __shared__ float aw[H_ * H_];

    for (int i = tid; i < H_ * D_; i += ATTN_THREADS) {
        const int h = i >> 6, d = i & 63;
        qs[i] = g_qkr[(((size_t)(b * H_ + h)) << 13) + s * D_ + d];
        ks[i] = g_qkr[(((size_t)(96 + b * H_ + h)) << 13) + s * D_ + d];
        vs[i] = g_v[(size_t)bs * E_ + i];
    }
    __syncthreads();

    if (tid < H_ * H_) {
        const int h = tid / H_, g = tid % H_;
        float acc = 0.0f;
        #pragma unroll
        for (int d = 0; d < D_; d++) acc += qs[h * D_ + d] * ks[g * D_ + d];
        aw[tid] = acc * 0.125f + mask[b * (H_ * H_) + tid];
    }
    __syncthreads();

    if (tid < H_) {
        float mx = -3.0e38f;
        #pragma unroll
        for (int g = 0; g < H_; g++) mx = fmaxf(mx, aw[tid * H_ + g]);
        float e[H_];
        float sum = 0.0f;
        #pragma unroll
        for (int g = 0; g < H_; g++) { e[g] = expf(aw[tid * H_ + g] - mx); sum += e[g]; }
        const float inv = 1.0f / sum;
        #pragma unroll
        for (int g = 0; g < H_; g++) aw[tid * H_ + g] = e[g] * inv;
    }
    __syncthreads();

    if (write_attn && tid < H_ * H_)
        attn_out[(size_t)bs * (H_ * H_) + tid] = aw[tid];

    for (int i = tid; i < H_ * D_; i += ATTN_THREADS) {
        const int h = i >> 6, d = i & 63;
        float acc = 0.0f;
        #pragma unroll
        for (int g = 0; g < H_; g++) acc += aw[h * H_ + g] * vs[g * D_ + d];
        g_ctx[(size_t)b * (H_ * S_ * D_) + h * (S_ * D_) + s * D_ + d] = acc;
    }
}

// ---------------- launch ----------------
extern "C" void kernel_launch(void* const* d_in, const int* in_sizes, int n_in,
                              void* d_out, int out_size)
{
    const float* hidden = (const float*)d_in[0];
    const float* R      = (const float*)d_in[1];
    const float* mask   = (const float*)d_in[2];
    const float* Wq     = (const float*)d_in[3];
    const float* Wk     = (const float*)d_in[4];
    const float* Wv     = (const float*)d_in[5];
    const float* Wo     = (const float*)d_in[6];
    float* out = (float*)d_out;

    const int OUT_ELEMS  = B_ * S_ * E_;
    const int ATTN_ELEMS = B_ * S_ * H_ * H_;
    const int write_attn = (out_size >= OUT_ELEMS + ATTN_ELEMS) ? 1 : 0;

    // 1) WMMA QKV projections, 64x64 tiles (q,k -> split rotated layout; v -> g_v)
    wproj_kernel<<<dim3(E_ / 64, BSROWS / 64, 3), 256>>>(hidden, Wq, Wk, Wv);

    // 2) WMMA rotation v4: 96x64 tiles, double-buffered smem, 1 sync/chunk, occ 2
    rot_wmma_kernel<<<dim3(SD_ / RBN, 2), 256>>>(R);

    // 3) per-position head-axis attention
    attn_kernel<<<BSROWS, ATTN_THREADS>>>(mask, out + OUT_ELEMS, write_attn);

    // 4) WMMA output projection -> d_out
    wfinal_kernel<<<dim3(E_ / 64, BSROWS / 64), 256>>>(Wo, out);
}